// round 4
// baseline (speedup 1.0000x reference)
#include <cuda_runtime.h>
#include <math_constants.h>
#include <cstdint>

// KNN_18614388261211 — farthest-(k+1) selection, drop rank 0.
// x: (8,2048,3) f32 -> BN=16384 points, k=16.
// out: [ dists (BN*16 f32 = pair values) | idx (BN*16 as f32) ]

#define BN       16384
#define KOUT     16
#define R        8                 // rows per warp
#define NW       16                // warps per block
#define NTHREADS (NW * 32)
#define NBLOCKS  (BN / (NW * R))   // 128
#define NITER    (BN / 32)         // 512 warp-iterations over candidates
#define SMEM_BYTES (BN * 3 * 4)    // 192 KB SoA: xs, ys, zs
#define SLACK    1e-3f             // conservative filter slack (>> max fma-vs-rn error)

__device__ __forceinline__ float fneg(float v) {
    return __int_as_float(__float_as_int(v) ^ 0x80000000u);
}

__global__ __launch_bounds__(NTHREADS, 1)
void knn_kernel(const float* __restrict__ x, float* __restrict__ out) {
    extern __shared__ float smem[];
    float* __restrict__ xs = smem;
    float* __restrict__ ys = smem + BN;
    float* __restrict__ zs = smem + 2 * BN;

    for (int p = threadIdx.x; p < BN; p += NTHREADS) {
        xs[p] = x[3 * p + 0];
        ys[p] = x[3 * p + 1];
        zs[p] = x[3 * p + 2];
    }
    __syncthreads();

    const int lane = threadIdx.x & 31;
    const int warp = threadIdx.x >> 5;
    const int row0 = (blockIdx.x * NW + warp) * R;
    const unsigned FULL = 0xffffffffu;

    // Per-row scalar state:
    //   px2,py2,pz2 = doubled coords; nsqi = -sqi;
    //   cR = -sqi - T - SLACK  (filter constant: admit iff pv_fast < T + SLACK,
    //        a strict SUPERSET of exact qualifiers incl. ties; -INF while T=+INF);
    //   lv/lj = warp-distributed sorted list (lane l in 0..16 holds rank l).
    float px2[R], py2[R], pz2[R], nsqi[R], cR[R], lv[R];
    int   lj[R];

#pragma unroll
    for (int r = 0; r < R; r++) {
        const float px = xs[row0 + r], py = ys[row0 + r], pz = zs[row0 + r];
        const float sqi = __fadd_rn(__fadd_rn(__fmul_rn(px, px), __fmul_rn(py, py)),
                                    __fmul_rn(pz, pz));
        px2[r] = __fadd_rn(px, px);   // exact doubling
        py2[r] = __fadd_rn(py, py);
        pz2[r] = __fadd_rn(pz, pz);
        nsqi[r] = fneg(sqi);
        cR[r]   = -CUDART_INF_F;      // T = +INF: admit everything
        lv[r] = CUDART_INF_F;
        lj[r] = 0x7fffffff;
    }

    for (int t = 0; t < NITER; t++) {
        const int j = t * 32 + lane;
        const float qx = xs[j];
        const float qy = ys[j];
        const float qz = zs[j];
        // Fast (fma-contracted) sqj for the filter only.
        const float sqjf = __fmaf_rn(qx, qx, __fmaf_rn(qy, qy, __fmul_rn(qz, qz)));

        unsigned rowmask = 0;
#pragma unroll
        for (int r = 0; r < R; r++) {
            // acc = 2*dot + (-sqi - T - SLACK) - sqj = (pv_fast - T) - SLACK
            // admit iff acc < 0  <=>  pv_fast < T + SLACK   (conservative superset)
            float acc = __fmaf_rn(pz2[r], qz,
                        __fmaf_rn(py2[r], qy,
                        __fmaf_rn(px2[r], qx, cR[r])));
            acc = __fsub_rn(acc, sqjf);
            if (__float_as_int(acc) < 0) rowmask |= (1u << r);
        }

        if (__any_sync(FULL, rowmask != 0)) {
            // Exact -sqj once per slow-path entry (rn, left-assoc, no fma).
            const float nsqj = fneg(__fadd_rn(__fadd_rn(__fmul_rn(qx, qx),
                                                        __fmul_rn(qy, qy)),
                                              __fmul_rn(qz, qz)));
            unsigned rmask = __reduce_or_sync(FULL, rowmask);
            while (rmask) {
                const int r = __ffs(rmask) - 1;
                rmask &= rmask - 1;
                unsigned b = __ballot_sync(FULL, (rowmask >> r) & 1u);
                // Exact pv: dot2x == 2*dot exactly (power-of-2 scaling commutes
                // with RN), so pv is bit-identical to the reference expression
                // ((dot+dot) - sqi) - sqj.
                const float dot2x = __fadd_rn(__fadd_rn(__fmul_rn(px2[r], qx),
                                                        __fmul_rn(py2[r], qy)),
                                              __fmul_rn(pz2[r], qz));
                const float pv = __fadd_rn(__fadd_rn(dot2x, nsqi[r]), nsqj);
                bool inserted = false;
                while (b) {
                    const int src = __ffs(b) - 1;
                    b &= b - 1;
                    const float nv = __shfl_sync(FULL, pv, src);
                    const int   nj = t * 32 + src;
                    // Insert (nv,nj) if it beats the list (exact comparator;
                    // filter false-positives produce im==0 and are dropped).
                    const bool after = (lane <= 16) &&
                        ((lv[r] > nv) || (lv[r] == nv && lj[r] > nj));
                    const unsigned im = __ballot_sync(FULL, after) & 0x1ffffu;
                    const float upv = __shfl_up_sync(FULL, lv[r], 1);
                    const int   upj = __shfl_up_sync(FULL, lj[r], 1);
                    if (im) {
                        const int pos = __ffs(im) - 1;
                        if (lane <= 16) {
                            if (lane > pos)       { lv[r] = upv; lj[r] = upj; }
                            else if (lane == pos) { lv[r] = nv;  lj[r] = nj;  }
                        }
                        inserted = true;
                    }
                }
                if (inserted) {
                    const float nt = __shfl_sync(FULL, lv[r], 16);
                    // cR = (-sqi - T) - SLACK   (conservative superset filter)
                    cR[r] = __fsub_rn(__fadd_rn(nsqi[r], fneg(nt)), SLACK);
                }
            }
        }
    }

    // Ranks 1..16 are the output (rank 0 dropped by the reference).
#pragma unroll
    for (int r = 0; r < R; r++) {
        if (lane >= 1 && lane <= 16) {
            const int row = row0 + r;
            out[(size_t)row * KOUT + (lane - 1)] = lv[r];
            out[(size_t)BN * KOUT + (size_t)row * KOUT + (lane - 1)] = (float)lj[r];
        }
    }
}

extern "C" void kernel_launch(void* const* d_in, const int* in_sizes, int n_in,
                              void* d_out, int out_size) {
    const float* x = (const float*)d_in[0];
    float* out = (float*)d_out;
    cudaFuncSetAttribute(knn_kernel, cudaFuncAttributeMaxDynamicSharedMemorySize,
                         SMEM_BYTES);
    knn_kernel<<<NBLOCKS, NTHREADS, SMEM_BYTES>>>(x, out);
}

// round 5
// speedup vs baseline: 3.4552x; 3.4552x over previous
#include <cuda_runtime.h>
#include <math_constants.h>
#include <cstdint>

// KNN_18614388261211 — farthest-(k+1) selection, drop rank 0.
// x: (8,2048,3) f32 -> BN=16384 points, k=16.
// out: [ dists (BN*16 f32 = pair values) | idx (BN*16 as f32) ]
//
// R5: identical math to R4 (which passed: rel_err 4e-8) but the slow path is a
// compile-time-unrolled loop over rows, so ALL per-row arrays are indexed with
// constants and live in registers. R4's runtime indexing (r = ffs(mask)) pushed
// the arrays to local memory -> 848 GB/s of spill traffic.

#define BN       16384
#define KOUT     16
#define R        8                 // rows per warp
#define NW       16                // warps per block
#define NTHREADS (NW * 32)
#define NBLOCKS  (BN / (NW * R))   // 128
#define NITER    (BN / 32)         // 512 warp-iterations over candidates
#define SMEM_BYTES (BN * 3 * 4)    // 192 KB SoA: xs, ys, zs
#define SLACK    1e-3f             // conservative filter slack (>> max fma-vs-rn error)

__device__ __forceinline__ float fneg(float v) {
    return __int_as_float(__float_as_int(v) ^ 0x80000000u);
}

__global__ __launch_bounds__(NTHREADS, 1)
void knn_kernel(const float* __restrict__ x, float* __restrict__ out) {
    extern __shared__ float smem[];
    float* __restrict__ xs = smem;
    float* __restrict__ ys = smem + BN;
    float* __restrict__ zs = smem + 2 * BN;

    for (int p = threadIdx.x; p < BN; p += NTHREADS) {
        xs[p] = x[3 * p + 0];
        ys[p] = x[3 * p + 1];
        zs[p] = x[3 * p + 2];
    }
    __syncthreads();

    const int lane = threadIdx.x & 31;
    const int warp = threadIdx.x >> 5;
    const int row0 = (blockIdx.x * NW + warp) * R;
    const unsigned FULL = 0xffffffffu;

    // Per-row scalar state — every access below uses a COMPILE-TIME index.
    float px2[R], py2[R], pz2[R], nsqi[R], cR[R], lv[R];
    int   lj[R];

#pragma unroll
    for (int r = 0; r < R; r++) {
        const float px = xs[row0 + r], py = ys[row0 + r], pz = zs[row0 + r];
        const float sqi = __fadd_rn(__fadd_rn(__fmul_rn(px, px), __fmul_rn(py, py)),
                                    __fmul_rn(pz, pz));
        px2[r] = __fadd_rn(px, px);   // exact doubling
        py2[r] = __fadd_rn(py, py);
        pz2[r] = __fadd_rn(pz, pz);
        nsqi[r] = fneg(sqi);
        cR[r]   = -CUDART_INF_F;      // T = +INF: admit everything
        lv[r] = CUDART_INF_F;         // lane l (0..16) holds rank-l; 17..31 sentinels
        lj[r] = 0x7fffffff;
    }

    for (int t = 0; t < NITER; t++) {
        const int j = t * 32 + lane;
        const float qx = xs[j];
        const float qy = ys[j];
        const float qz = zs[j];
        // Fast (fma-contracted) sqj for the filter only.
        const float sqjf = __fmaf_rn(qx, qx, __fmaf_rn(qy, qy, __fmul_rn(qz, qz)));

        unsigned rowmask = 0;
#pragma unroll
        for (int r = 0; r < R; r++) {
            // acc = 2*dot + (-sqi - T - SLACK) - sqj = (pv_fast - T) - SLACK
            // admit iff acc < 0  <=>  pv_fast < T + SLACK  (superset of exact)
            float acc = __fmaf_rn(pz2[r], qz,
                        __fmaf_rn(py2[r], qy,
                        __fmaf_rn(px2[r], qx, cR[r])));
            acc = __fsub_rn(acc, sqjf);
            if (__float_as_int(acc) < 0) rowmask |= (1u << r);
        }

        if (__any_sync(FULL, rowmask != 0)) {
            // Exact -sqj once per slow-path entry (rn, left-assoc, no fma).
            const float nsqj = fneg(__fadd_rn(__fadd_rn(__fmul_rn(qx, qx),
                                                        __fmul_rn(qy, qy)),
                                              __fmul_rn(qz, qz)));
#pragma unroll
            for (int r = 0; r < R; r++) {      // r is a COMPILE-TIME constant here
                unsigned b = __ballot_sync(FULL, (rowmask >> r) & 1u);
                if (!b) continue;              // warp-uniform (b uniform)
                // Exact pv: dot2x == 2*dot exactly (power-of-2 scaling commutes
                // with RN) -> pv bit-identical to ((dot+dot) - sqi) - sqj.
                const float dot2x = __fadd_rn(__fadd_rn(__fmul_rn(px2[r], qx),
                                                        __fmul_rn(py2[r], qy)),
                                              __fmul_rn(pz2[r], qz));
                const float pv = __fadd_rn(__fadd_rn(dot2x, nsqi[r]), nsqj);
                bool inserted = false;
                while (b) {
                    const int src = __ffs(b) - 1;
                    b &= b - 1;
                    const float nv = __shfl_sync(FULL, pv, src);
                    const int   nj = t * 32 + src;
                    // Exact comparator; filter false-positives give im==0.
                    const bool after = (lane <= 16) &&
                        ((lv[r] > nv) || (lv[r] == nv && lj[r] > nj));
                    const unsigned im = __ballot_sync(FULL, after) & 0x1ffffu;
                    const float upv = __shfl_up_sync(FULL, lv[r], 1);
                    const int   upj = __shfl_up_sync(FULL, lj[r], 1);
                    if (im) {
                        const int pos = __ffs(im) - 1;
                        if (lane <= 16) {
                            if (lane > pos)       { lv[r] = upv; lj[r] = upj; }
                            else if (lane == pos) { lv[r] = nv;  lj[r] = nj;  }
                        }
                        inserted = true;
                    }
                }
                if (inserted) {
                    const float nt = __shfl_sync(FULL, lv[r], 16);
                    // cR = (-sqi - T) - SLACK   (conservative superset filter)
                    cR[r] = __fsub_rn(__fadd_rn(nsqi[r], fneg(nt)), SLACK);
                }
            }
        }
    }

    // Ranks 1..16 are the output (rank 0 dropped by the reference).
#pragma unroll
    for (int r = 0; r < R; r++) {
        if (lane >= 1 && lane <= 16) {
            const int row = row0 + r;
            out[(size_t)row * KOUT + (lane - 1)] = lv[r];
            out[(size_t)BN * KOUT + (size_t)row * KOUT + (lane - 1)] = (float)lj[r];
        }
    }
}

extern "C" void kernel_launch(void* const* d_in, const int* in_sizes, int n_in,
                              void* d_out, int out_size) {
    const float* x = (const float*)d_in[0];
    float* out = (float*)d_out;
    cudaFuncSetAttribute(knn_kernel, cudaFuncAttributeMaxDynamicSharedMemorySize,
                         SMEM_BYTES);
    knn_kernel<<<NBLOCKS, NTHREADS, SMEM_BYTES>>>(x, out);
}

// round 6
// speedup vs baseline: 3.6330x; 1.0515x over previous
#include <cuda_runtime.h>
#include <math_constants.h>
#include <cstdint>

// KNN_18614388261211 — farthest-(k+1) selection, drop rank 0.
// x: (8,2048,3) f32 -> BN=16384 points, k=16.
// out: [ dists (BN*16 f32 = pair values) | idx (BN*16 as f32) ]
//
// R6: hot-loop restructure vs R5 (355us):
//   - min-reduce m_r across rows, single compare vs shared sqjf (4 ops/row-cand)
//   - software-pipelined candidate loads (LDS latency hidden under row FMAs)
// Slow path (exact comparator + insertion) identical to R5.

#define BN       16384
#define KOUT     16
#define R        8                 // rows per warp
#define NW       16                // warps per block
#define NTHREADS (NW * 32)
#define NBLOCKS  (BN / (NW * R))   // 128
#define NITER    (BN / 32)         // 512 warp-iterations over candidates
#define SMEM_BYTES (BN * 3 * 4)    // 192 KB SoA: xs, ys, zs
#define SLACK    1e-3f             // conservative filter slack (>> max fma-vs-rn error)

__device__ __forceinline__ float fneg(float v) {
    return __int_as_float(__float_as_int(v) ^ 0x80000000u);
}

__global__ __launch_bounds__(NTHREADS, 1)
void knn_kernel(const float* __restrict__ x, float* __restrict__ out) {
    extern __shared__ float smem[];
    float* __restrict__ xs = smem;
    float* __restrict__ ys = smem + BN;
    float* __restrict__ zs = smem + 2 * BN;

    for (int p = threadIdx.x; p < BN; p += NTHREADS) {
        xs[p] = x[3 * p + 0];
        ys[p] = x[3 * p + 1];
        zs[p] = x[3 * p + 2];
    }
    __syncthreads();

    const int lane = threadIdx.x & 31;
    const int warp = threadIdx.x >> 5;
    const int row0 = (blockIdx.x * NW + warp) * R;
    const unsigned FULL = 0xffffffffu;

    // Per-row scalar state — all compile-time indexed (R5 lesson: no LMEM).
    //   cR = -sqi - T - SLACK; admit-any iff min_r m_r < sqjf, where
    //   m_r = 2*dot_r + cR_r (fma-contracted).
    float px2[R], py2[R], pz2[R], nsqi[R], cR[R], lv[R];
    int   lj[R];

#pragma unroll
    for (int r = 0; r < R; r++) {
        const float px = xs[row0 + r], py = ys[row0 + r], pz = zs[row0 + r];
        const float sqi = __fadd_rn(__fadd_rn(__fmul_rn(px, px), __fmul_rn(py, py)),
                                    __fmul_rn(pz, pz));
        px2[r] = __fadd_rn(px, px);   // exact doubling
        py2[r] = __fadd_rn(py, py);
        pz2[r] = __fadd_rn(pz, pz);
        nsqi[r] = fneg(sqi);
        cR[r]   = -CUDART_INF_F;      // T = +INF: admit everything
        lv[r] = CUDART_INF_F;         // lane l (0..16) holds rank-l; 17..31 sentinels
        lj[r] = 0x7fffffff;
    }

    // Software pipeline: preload iteration 0's candidate.
    float qxn = xs[lane], qyn = ys[lane], qzn = zs[lane];

    for (int t = 0; t < NITER; t++) {
        const float qx = qxn, qy = qyn, qz = qzn;
        // Prefetch next iteration's candidate (clamped index keeps it branchless).
        const int jn = (t + 1 < NITER) ? (t + 1) * 32 + lane : lane;
        qxn = xs[jn]; qyn = ys[jn]; qzn = zs[jn];

        // Shared per-candidate sqj (fma-contracted, filter only).
        const float sqjf = __fmaf_rn(qx, qx, __fmaf_rn(qy, qy, __fmul_rn(qz, qz)));

        // min over rows of m_r; qualify iff mn < sqjf.
        float mn = CUDART_INF_F;
#pragma unroll
        for (int r = 0; r < R; r++) {
            const float m = __fmaf_rn(pz2[r], qz,
                            __fmaf_rn(py2[r], qy,
                            __fmaf_rn(px2[r], qx, cR[r])));
            mn = fminf(mn, m);
        }

        if (__any_sync(FULL, mn < sqjf)) {
            // Exact -sqj once per slow-path entry (rn, left-assoc, no fma).
            const float nsqj = fneg(__fadd_rn(__fadd_rn(__fmul_rn(qx, qx),
                                                        __fmul_rn(qy, qy)),
                                              __fmul_rn(qz, qz)));
#pragma unroll
            for (int r = 0; r < R; r++) {      // compile-time r
                // Recompute m_r with the IDENTICAL contraction as the hot loop.
                const float m = __fmaf_rn(pz2[r], qz,
                                __fmaf_rn(py2[r], qy,
                                __fmaf_rn(px2[r], qx, cR[r])));
                unsigned b = __ballot_sync(FULL, m < sqjf);
                if (!b) continue;              // warp-uniform
                // Exact pv: dot2x == 2*dot exactly (power-of-2 scaling commutes
                // with RN) -> pv bit-identical to ((dot+dot) - sqi) - sqj.
                const float dot2x = __fadd_rn(__fadd_rn(__fmul_rn(px2[r], qx),
                                                        __fmul_rn(py2[r], qy)),
                                              __fmul_rn(pz2[r], qz));
                const float pv = __fadd_rn(__fadd_rn(dot2x, nsqi[r]), nsqj);
                bool inserted = false;
                while (b) {
                    const int src = __ffs(b) - 1;
                    b &= b - 1;
                    const float nv = __shfl_sync(FULL, pv, src);
                    const int   nj = t * 32 + src;
                    // Exact comparator; filter false-positives give im==0.
                    const bool after = (lane <= 16) &&
                        ((lv[r] > nv) || (lv[r] == nv && lj[r] > nj));
                    const unsigned im = __ballot_sync(FULL, after) & 0x1ffffu;
                    const float upv = __shfl_up_sync(FULL, lv[r], 1);
                    const int   upj = __shfl_up_sync(FULL, lj[r], 1);
                    if (im) {
                        const int pos = __ffs(im) - 1;
                        if (lane <= 16) {
                            if (lane > pos)       { lv[r] = upv; lj[r] = upj; }
                            else if (lane == pos) { lv[r] = nv;  lj[r] = nj;  }
                        }
                        inserted = true;
                    }
                }
                if (inserted) {
                    const float nt = __shfl_sync(FULL, lv[r], 16);
                    // cR = (-sqi - T) - SLACK   (conservative superset filter)
                    cR[r] = __fsub_rn(__fadd_rn(nsqi[r], fneg(nt)), SLACK);
                }
            }
        }
    }

    // Ranks 1..16 are the output (rank 0 dropped by the reference).
#pragma unroll
    for (int r = 0; r < R; r++) {
        if (lane >= 1 && lane <= 16) {
            const int row = row0 + r;
            out[(size_t)row * KOUT + (lane - 1)] = lv[r];
            out[(size_t)BN * KOUT + (size_t)row * KOUT + (lane - 1)] = (float)lj[r];
        }
    }
}

extern "C" void kernel_launch(void* const* d_in, const int* in_sizes, int n_in,
                              void* d_out, int out_size) {
    const float* x = (const float*)d_in[0];
    float* out = (float*)d_out;
    cudaFuncSetAttribute(knn_kernel, cudaFuncAttributeMaxDynamicSharedMemorySize,
                         SMEM_BYTES);
    knn_kernel<<<NBLOCKS, NTHREADS, SMEM_BYTES>>>(x, out);
}

// round 8
// speedup vs baseline: 4.9823x; 1.3714x over previous
#include <cuda_runtime.h>
#include <math_constants.h>
#include <cstdint>

// KNN_18614388261211 — farthest-(k+1) selection, drop rank 0.
// x: (8,2048,3) f32 -> BN=16384 points, k=16.
// out: [ dists (BN*16 f32 = pair values) | idx (BN*16 as f32) ]
//
// R7 vs R6 (337us):
//   - 1024 threads (NW=32, R=4): occupancy 2x for latency hiding (issue was 51%)
//   - hot loop keeps m[r] in regs; slow path reuses them (no FMA recompute)
//   - slow path: lane hitmask + one reduce_or, ballot only for rows that hit
//   - exact insertion comparator unchanged (bit-identical results)

#define BN       16384
#define KOUT     16
#define R        4                 // rows per warp
#define NW       32                // warps per block
#define NTHREADS (NW * 32)         // 1024
#define NBLOCKS  (BN / (NW * R))   // 128
#define NITER    (BN / 32)         // 512 warp-iterations over candidates
#define SMEM_BYTES (BN * 3 * 4)    // 192 KB SoA: xs, ys, zs
#define SLACK    1e-3f             // conservative filter slack (>> max fma-vs-rn error)

__device__ __forceinline__ float fneg(float v) {
    return __int_as_float(__float_as_int(v) ^ 0x80000000u);
}

__global__ __launch_bounds__(NTHREADS, 1)
void knn_kernel(const float* __restrict__ x, float* __restrict__ out) {
    extern __shared__ float smem[];
    float* __restrict__ xs = smem;
    float* __restrict__ ys = smem + BN;
    float* __restrict__ zs = smem + 2 * BN;

    for (int p = threadIdx.x; p < BN; p += NTHREADS) {
        xs[p] = x[3 * p + 0];
        ys[p] = x[3 * p + 1];
        zs[p] = x[3 * p + 2];
    }
    __syncthreads();

    const int lane = threadIdx.x & 31;
    const int warp = threadIdx.x >> 5;
    const int row0 = (blockIdx.x * NW + warp) * R;
    const unsigned FULL = 0xffffffffu;

    // Per-row scalar state — all compile-time indexed (no LMEM).
    float px2[R], py2[R], pz2[R], nsqi[R], cR[R], lv[R];
    int   lj[R];

#pragma unroll
    for (int r = 0; r < R; r++) {
        const float px = xs[row0 + r], py = ys[row0 + r], pz = zs[row0 + r];
        const float sqi = __fadd_rn(__fadd_rn(__fmul_rn(px, px), __fmul_rn(py, py)),
                                    __fmul_rn(pz, pz));
        px2[r] = __fadd_rn(px, px);   // exact doubling
        py2[r] = __fadd_rn(py, py);
        pz2[r] = __fadd_rn(pz, pz);
        nsqi[r] = fneg(sqi);
        cR[r]   = -CUDART_INF_F;      // T = +INF: admit everything
        lv[r] = CUDART_INF_F;         // lane l (0..16) holds rank-l; 17..31 sentinels
        lj[r] = 0x7fffffff;
    }

    // Software pipeline: preload iteration 0's candidate.
    float qxn = xs[lane], qyn = ys[lane], qzn = zs[lane];

    for (int t = 0; t < NITER; t++) {
        const float qx = qxn, qy = qyn, qz = qzn;
        const int jn = (((t + 1) & (NITER - 1)) << 5) + lane;
        qxn = xs[jn]; qyn = ys[jn]; qzn = zs[jn];

        // Shared per-candidate sqj (fma-contracted, filter only).
        const float sqjf = __fmaf_rn(qx, qx, __fmaf_rn(qy, qy, __fmul_rn(qz, qz)));

        // m[r] = 2*dot_r + (-sqi_r - T_r - SLACK); kept alive for the slow path.
        float m[R];
        float mn = CUDART_INF_F;
#pragma unroll
        for (int r = 0; r < R; r++) {
            m[r] = __fmaf_rn(pz2[r], qz,
                   __fmaf_rn(py2[r], qy,
                   __fmaf_rn(px2[r], qx, cR[r])));
            mn = fminf(mn, m[r]);
        }

        if (__any_sync(FULL, mn < sqjf)) {
            // Lane-local hitmask from the SAME m[r] values (no recompute).
            unsigned hm = 0;
#pragma unroll
            for (int r = 0; r < R; r++)
                if (m[r] < sqjf) hm |= (1u << r);
            const unsigned wm = __reduce_or_sync(FULL, hm);  // warp-uniform

            // Exact -sqj once per slow-path entry (rn, left-assoc, no fma).
            const float nsqj = fneg(__fadd_rn(__fadd_rn(__fmul_rn(qx, qx),
                                                        __fmul_rn(qy, qy)),
                                              __fmul_rn(qz, qz)));
#pragma unroll
            for (int r = 0; r < R; r++) {      // compile-time r
                if (!((wm >> r) & 1u)) continue;   // warp-uniform skip
                unsigned b = __ballot_sync(FULL, (hm >> r) & 1u);
                // Exact pv: dot2x == 2*dot exactly (power-of-2 scaling commutes
                // with RN) -> pv bit-identical to ((dot+dot) - sqi) - sqj.
                const float dot2x = __fadd_rn(__fadd_rn(__fmul_rn(px2[r], qx),
                                                        __fmul_rn(py2[r], qy)),
                                              __fmul_rn(pz2[r], qz));
                const float pv = __fadd_rn(__fadd_rn(dot2x, nsqi[r]), nsqj);
                bool inserted = false;
                while (b) {
                    const int src = __ffs(b) - 1;
                    b &= b - 1;
                    const float nv = __shfl_sync(FULL, pv, src);
                    const int   nj = (t << 5) + src;
                    // Exact comparator; filter false-positives give im==0.
                    const bool after = (lane <= 16) &&
                        ((lv[r] > nv) || (lv[r] == nv && lj[r] > nj));
                    const unsigned im = __ballot_sync(FULL, after) & 0x1ffffu;
                    const float upv = __shfl_up_sync(FULL, lv[r], 1);
                    const int   upj = __shfl_up_sync(FULL, lj[r], 1);
                    if (im) {
                        const int pos = __ffs(im) - 1;
                        if (lane <= 16) {
                            if (lane > pos)       { lv[r] = upv; lj[r] = upj; }
                            else if (lane == pos) { lv[r] = nv;  lj[r] = nj;  }
                        }
                        inserted = true;
                    }
                }
                if (inserted) {
                    const float nt = __shfl_sync(FULL, lv[r], 16);
                    // cR = (-sqi - T) - SLACK   (conservative superset filter)
                    cR[r] = __fsub_rn(__fadd_rn(nsqi[r], fneg(nt)), SLACK);
                }
            }
        }
    }

    // Ranks 1..16 are the output (rank 0 dropped by the reference).
#pragma unroll
    for (int r = 0; r < R; r++) {
        if (lane >= 1 && lane <= 16) {
            const int row = row0 + r;
            out[(size_t)row * KOUT + (lane - 1)] = lv[r];
            out[(size_t)BN * KOUT + (size_t)row * KOUT + (lane - 1)] = (float)lj[r];
        }
    }
}

extern "C" void kernel_launch(void* const* d_in, const int* in_sizes, int n_in,
                              void* d_out, int out_size) {
    const float* x = (const float*)d_in[0];
    float* out = (float*)d_out;
    cudaFuncSetAttribute(knn_kernel, cudaFuncAttributeMaxDynamicSharedMemorySize,
                         SMEM_BYTES);
    knn_kernel<<<NBLOCKS, NTHREADS, SMEM_BYTES>>>(x, out);
}

// round 9
// speedup vs baseline: 5.2490x; 1.0535x over previous
#include <cuda_runtime.h>
#include <math_constants.h>
#include <cstdint>

// KNN_18614388261211 — farthest-(k+1) selection, drop rank 0.
// x: (8,2048,3) f32 -> BN=16384 points, k=16.
// out: [ dists (BN*16 f32 = pair values) | idx (BN*16 as f32) ]
//
// R8 vs R7 (246us): candidate pairing — 2 candidates per lane per iteration.
//   - xy stored as float2 SoA: LDS.128 loads both candidates' xy, LDS.64 both z
//   - loop control / any-vote amortized over 2 candidates
//   - slow path gated per candidate, reuses hot-loop m[] registers
//   - exact insertion comparator unchanged (bit-identical results)

#define BN       16384
#define KOUT     16
#define R        4                 // rows per warp
#define NW       32                // warps per block
#define NTHREADS (NW * 32)         // 1024
#define NBLOCKS  (BN / (NW * R))   // 128
#define NITER2   (BN / 64)         // 256 iterations, 64 candidates each
#define SMEM_BYTES (BN * 3 * 4)    // 192 KB: float2 xy[BN] + float z[BN]
#define SLACK    1e-3f             // conservative filter slack (>> max fma-vs-rn error)

__device__ __forceinline__ float fneg(float v) {
    return __int_as_float(__float_as_int(v) ^ 0x80000000u);
}

// Slow path for one candidate (QX,QY,QZ) with hot-loop filter values MARR[].
// Macro (not function) so lv/lj/cR/nsqi stay compile-time indexed -> registers.
#define PROCESS_CAND(QX, QY, QZ, MARR, SQJF, NJBASE)                            \
    do {                                                                        \
        const float nsqj_ = fneg(__fadd_rn(__fadd_rn(__fmul_rn((QX), (QX)),     \
                                                     __fmul_rn((QY), (QY))),    \
                                           __fmul_rn((QZ), (QZ))));             \
        _Pragma("unroll")                                                       \
        for (int r_ = 0; r_ < R; r_++) {                                        \
            unsigned b_ = __ballot_sync(FULL, MARR[r_] < (SQJF));               \
            if (!b_) continue;                                                  \
            const float dot2x_ = __fadd_rn(__fadd_rn(__fmul_rn(px2[r_], (QX)),  \
                                                     __fmul_rn(py2[r_], (QY))), \
                                           __fmul_rn(pz2[r_], (QZ)));           \
            const float pv_ = __fadd_rn(__fadd_rn(dot2x_, nsqi[r_]), nsqj_);    \
            bool inserted_ = false;                                             \
            while (b_) {                                                        \
                const int src_ = __ffs(b_) - 1;                                 \
                b_ &= b_ - 1;                                                   \
                const float nv_ = __shfl_sync(FULL, pv_, src_);                 \
                const int   nj_ = (NJBASE) + 2 * src_;                          \
                const bool after_ = (lane <= 16) &&                             \
                    ((lv[r_] > nv_) || (lv[r_] == nv_ && lj[r_] > nj_));        \
                const unsigned im_ = __ballot_sync(FULL, after_) & 0x1ffffu;    \
                const float upv_ = __shfl_up_sync(FULL, lv[r_], 1);             \
                const int   upj_ = __shfl_up_sync(FULL, lj[r_], 1);             \
                if (im_) {                                                      \
                    const int pos_ = __ffs(im_) - 1;                            \
                    if (lane <= 16) {                                           \
                        if (lane > pos_)       { lv[r_] = upv_; lj[r_] = upj_; }\
                        else if (lane == pos_) { lv[r_] = nv_;  lj[r_] = nj_;  }\
                    }                                                           \
                    inserted_ = true;                                           \
                }                                                               \
            }                                                                   \
            if (inserted_) {                                                    \
                const float nt_ = __shfl_sync(FULL, lv[r_], 16);                \
                cR[r_] = __fsub_rn(__fadd_rn(nsqi[r_], fneg(nt_)), SLACK);      \
            }                                                                   \
        }                                                                       \
    } while (0)

__global__ __launch_bounds__(NTHREADS, 1)
void knn_kernel(const float* __restrict__ x, float* __restrict__ out) {
    extern __shared__ float smem[];
    float2* __restrict__ sxy = reinterpret_cast<float2*>(smem);  // [BN]
    float*  __restrict__ sz  = smem + 2 * BN;                    // [BN]

    for (int p = threadIdx.x; p < BN; p += NTHREADS) {
        sxy[p] = make_float2(x[3 * p + 0], x[3 * p + 1]);
        sz[p]  = x[3 * p + 2];
    }
    __syncthreads();

    const int lane = threadIdx.x & 31;
    const int warp = threadIdx.x >> 5;
    const int row0 = (blockIdx.x * NW + warp) * R;
    const unsigned FULL = 0xffffffffu;

    // Per-row scalar state — all compile-time indexed (no LMEM).
    float px2[R], py2[R], pz2[R], nsqi[R], cR[R], lv[R];
    int   lj[R];

#pragma unroll
    for (int r = 0; r < R; r++) {
        const float2 pxy = sxy[row0 + r];
        const float  pz  = sz[row0 + r];
        const float sqi = __fadd_rn(__fadd_rn(__fmul_rn(pxy.x, pxy.x),
                                              __fmul_rn(pxy.y, pxy.y)),
                                    __fmul_rn(pz, pz));
        px2[r] = __fadd_rn(pxy.x, pxy.x);   // exact doubling
        py2[r] = __fadd_rn(pxy.y, pxy.y);
        pz2[r] = __fadd_rn(pz, pz);
        nsqi[r] = fneg(sqi);
        cR[r]   = -CUDART_INF_F;            // T = +INF: admit everything
        lv[r] = CUDART_INF_F;               // lane l (0..16) holds rank-l
        lj[r] = 0x7fffffff;
    }

    for (int t = 0; t < NITER2; t++) {
        const int j0 = (t << 6) + (lane << 1);       // candidates j0, j0+1
        const float4 xy = *reinterpret_cast<const float4*>(sxy + j0); // LDS.128
        const float2 zz = *reinterpret_cast<const float2*>(sz + j0);  // LDS.64

        // Fast (fma-contracted) sqj per candidate (filter only).
        const float sqA = __fmaf_rn(xy.x, xy.x,
                          __fmaf_rn(xy.y, xy.y, __fmul_rn(zz.x, zz.x)));
        const float sqB = __fmaf_rn(xy.z, xy.z,
                          __fmaf_rn(xy.w, xy.w, __fmul_rn(zz.y, zz.y)));

        // m[r] = 2*dot_r + (-sqi_r - T_r - SLACK), per candidate.
        float mA[R], mB[R];
        float mnA = CUDART_INF_F, mnB = CUDART_INF_F;
#pragma unroll
        for (int r = 0; r < R; r++) {
            mA[r] = __fmaf_rn(pz2[r], zz.x,
                    __fmaf_rn(py2[r], xy.y,
                    __fmaf_rn(px2[r], xy.x, cR[r])));
            mB[r] = __fmaf_rn(pz2[r], zz.y,
                    __fmaf_rn(py2[r], xy.w,
                    __fmaf_rn(px2[r], xy.z, cR[r])));
            mnA = fminf(mnA, mA[r]);
            mnB = fminf(mnB, mB[r]);
        }

        const bool qA = mnA < sqA;
        const bool qB = mnB < sqB;
        if (__any_sync(FULL, qA || qB)) {
            const unsigned gA = __ballot_sync(FULL, qA);
            const unsigned gB = __ballot_sync(FULL, qB);
            const int njbase = t << 6;
            if (gA) PROCESS_CAND(xy.x, xy.y, zz.x, mA, sqA, njbase);
            if (gB) PROCESS_CAND(xy.z, xy.w, zz.y, mB, sqB, njbase + 1);
        }
    }

    // Ranks 1..16 are the output (rank 0 dropped by the reference).
#pragma unroll
    for (int r = 0; r < R; r++) {
        if (lane >= 1 && lane <= 16) {
            const int row = row0 + r;
            out[(size_t)row * KOUT + (lane - 1)] = lv[r];
            out[(size_t)BN * KOUT + (size_t)row * KOUT + (lane - 1)] = (float)lj[r];
        }
    }
}

extern "C" void kernel_launch(void* const* d_in, const int* in_sizes, int n_in,
                              void* d_out, int out_size) {
    const float* x = (const float*)d_in[0];
    float* out = (float*)d_out;
    cudaFuncSetAttribute(knn_kernel, cudaFuncAttributeMaxDynamicSharedMemorySize,
                         SMEM_BYTES);
    knn_kernel<<<NBLOCKS, NTHREADS, SMEM_BYTES>>>(x, out);
}